// round 2
// baseline (speedup 1.0000x reference)
#include <cuda_runtime.h>

// ---------------- problem constants ----------------
#define BB  8
#define SEQ 32768
#define HH  96
#define GG  384        // 4*HH
#define KW  16         // progress publish / consume granularity (timesteps)
#define HC  256        // head chunk
#define B4  4          // batches per recurrence CTA

typedef unsigned long long ull;

// ---------------- scratch (device globals; allocation is banned) ----------------
__device__ float g_h0seq[(size_t)BB * SEQ * HH];   // layer-0 hidden outputs
__device__ float g_xp1 [(size_t)BB * SEQ * GG];    // layer-1 input projections (incl. b1)
__device__ float g_h1seq[(size_t)BB * SEQ * HH];   // layer-1 hidden outputs

// progress flags (timesteps completed); reset by reset_kernel each replay
__device__ int g_prog0[BB];        // layer-0 recurrence progress
__device__ int g_progx[2 * BB];    // xp1 progress, [parity][batch]
__device__ int g_prog1[BB];        // layer-1 recurrence progress

// ---------------- packed f32x2 helpers ----------------
__device__ __forceinline__ ull ffma2(ull a, ull b, ull c) {
    ull d;
    asm("fma.rn.f32x2 %0, %1, %2, %3;" : "=l"(d) : "l"(a), "l"(b), "l"(c));
    return d;
}
__device__ __forceinline__ ull pack2(float x, float y) {
    ull v;
    asm("mov.b64 %0, {%1, %2};" : "=l"(v) : "f"(x), "f"(y));
    return v;
}
__device__ __forceinline__ void unpack2(ull v, float& x, float& y) {
    asm("mov.b64 {%0, %1}, %2;" : "=f"(x), "=f"(y) : "l"(v));
}

// ---------------- fast activations ----------------
__device__ __forceinline__ float sigmoid_f(float x) {
    float e = __expf(-x);
    return __fdividef(1.0f, 1.0f + e);
}
__device__ __forceinline__ float tanh_f(float x) {
    float e = __expf(2.0f * x);
    return 1.0f - __fdividef(2.0f, 1.0f + e);
}

// ---------------- weight row -> registers ----------------
__device__ __forceinline__ void load_row(ull* w, const float* rowp) {
    const ulonglong2* wp = (const ulonglong2*)rowp;
#pragma unroll
    for (int k = 0; k < 24; k++) {
        ulonglong2 v = __ldg(wp + k);
        w[2 * k]     = v.x;
        w[2 * k + 1] = v.y;
    }
}

// dot(w_row, h[0..95]) + init  using packed FMA; h must be 16B aligned
__device__ __forceinline__ float dotv(const ull* __restrict__ w,
                                      const float* __restrict__ hsh,
                                      float init) {
    ull a0 = pack2(init, 0.0f);
    ull a1 = 0ull;
    const ulonglong2* h4 = (const ulonglong2*)hsh;
#pragma unroll
    for (int k = 0; k < 24; k++) {
        ulonglong2 hv = h4[k];
        a0 = ffma2(w[2 * k],     hv.x, a0);
        a1 = ffma2(w[2 * k + 1], hv.y, a1);
    }
    float x0, y0, x1, y1;
    unpack2(a0, x0, y0);
    unpack2(a1, x1, y1);
    return (x0 + x1) + (y0 + y1);
}

// acquire-spin until *p >= target
__device__ __forceinline__ void wait_ge(int* p, int target) {
    while (atomicAdd(p, 0) < target) { __nanosleep(64); }
    __threadfence();
}

// ---------------- reset kernel (flags must be zero at start of every replay) ----------------
__global__ void reset_kernel() {
    int i = threadIdx.x;
    if (i < BB)     g_prog0[i] = 0;
    if (i < 2 * BB) g_progx[i] = 0;
    if (i < BB)     g_prog1[i] = 0;
}

// =====================================================================
// Mega-kernel: 28 blocks of 384 threads, all co-resident.
//   blocks  0..1  : layer-0 recurrence, 4 batches each
//   blocks  2..17 : xp1 workers, 2 per batch (parity-interleaved chunks)
//   blocks 18..19 : layer-1 recurrence, 4 batches each
//   blocks 20..27 : head workers, 1 per batch
// =====================================================================
__global__ void __launch_bounds__(GG, 1)
mega_kernel(const float* __restrict__ x,
            const float* __restrict__ Wih0, const float* __restrict__ Whh0,
            const float* __restrict__ bv0,
            const float* __restrict__ Wih1, const float* __restrict__ Whh1,
            const float* __restrict__ bv1,
            const float* __restrict__ h0in, const float* __restrict__ c0in,
            const float* __restrict__ head_w, const float* __restrict__ head_b,
            float* __restrict__ out)
{
    __shared__ __align__(16) float sh[B4 * HH + B4 * GG];   // 7680 B (xp role uses first 6144 B)
    const int bid = blockIdx.x;
    const int g   = threadIdx.x;

    if (bid < 2) {
        // ---------------- layer-0 recurrence, batches [4*bid, 4*bid+4) ----------------
        const int bbase = bid * B4;
        float* h_sh    = sh;             // [B4][HH]
        float* gate_sh = sh + B4 * HH;   // [B4][GG]

        ull w[48];
        load_row(w, Whh0 + g * HH);
        const float wih  = __ldg(&Wih0[g]);
        const float bias = __ldg(&bv0[g]);
        const int idx = g % HH;
        const bool is_g = (g >= 2 * HH) && (g < 3 * HH);   // warp-uniform

        float c[B4], xnext[B4];
        const float* xb[B4];
        float* hb[B4];
#pragma unroll
        for (int s = 0; s < B4; s++) {
            c[s] = __ldg(&c0in[idx]);
            if (g < HH) h_sh[s * HH + g] = __ldg(&h0in[g]);
            xb[s] = x + (size_t)(bbase + s) * SEQ;
            hb[s] = g_h0seq + (size_t)(bbase + s) * SEQ * HH;
            xnext[s] = __ldg(&xb[s][0]);
        }
        __syncthreads();

#pragma unroll 1
        for (int t = 0; t < SEQ; t++) {
            const int tn = (t + 1 < SEQ) ? (t + 1) : t;
#pragma unroll
            for (int s = 0; s < B4; s++) {
                float xt = xnext[s];
                xnext[s] = __ldg(&xb[s][tn]);
                float dot = dotv(w, h_sh + s * HH, fmaf(xt, wih, bias));
                gate_sh[s * GG + g] = is_g ? tanh_f(dot) : sigmoid_f(dot);
            }
            __syncthreads();
#pragma unroll
            for (int s = 0; s < B4; s++) {
                float iv = gate_sh[s * GG + idx];
                float fv = gate_sh[s * GG + idx + HH];
                float gv = gate_sh[s * GG + idx + 2 * HH];
                float ov = gate_sh[s * GG + idx + 3 * HH];
                c[s] = fmaf(fv, c[s], iv * gv);
                float hval = ov * tanh_f(c[s]);
                if (g < HH) {
                    h_sh[s * HH + g] = hval;
                    hb[s][(size_t)t * HH + g] = hval;
                }
            }
            __syncthreads();
            if (((t & (KW - 1)) == (KW - 1)) && g < B4) {
                __threadfence();
                atomicExch(&g_prog0[bbase + g], t + 1);
            }
        }
    } else if (bid < 18) {
        // ---------------- xp1 workers: xp1[b,t,g] = W_ih_1[g,:]·h0[b,t,:] + b1[g] ----------------
        const int i   = bid - 2;
        const int b   = i >> 1;
        const int par = i & 1;

        ull w[48];
        load_row(w, Wih1 + g * HH);
        const float bias = __ldg(&bv1[g]);
        const float* hbase = g_h0seq + (size_t)b * SEQ * HH;
        float* xpb = g_xp1 + (size_t)b * SEQ * GG;

#pragma unroll 1
        for (int t0 = par * KW; t0 < SEQ; t0 += 2 * KW) {
            if (g == 0) wait_ge(&g_prog0[b], t0 + KW);
            __syncthreads();
            // stage KW timesteps of h0 into shared (384 float4 = 16 steps x 96 floats)
            ((float4*)sh)[g] = ((const float4*)(hbase + (size_t)t0 * HH))[g];
            __syncthreads();
#pragma unroll 4
            for (int s = 0; s < KW; s++) {
                xpb[(size_t)(t0 + s) * GG + g] = dotv(w, sh + s * HH, bias);
            }
            __syncthreads();
            if (g == 0) {
                __threadfence();
                atomicExch(&g_progx[par * BB + b], t0 + KW);
            }
        }
    } else if (bid < 20) {
        // ---------------- layer-1 recurrence, batches [4*(bid-18), ...) ----------------
        const int bbase = (bid - 18) * B4;
        float* h_sh    = sh;
        float* gate_sh = sh + B4 * HH;

        ull w[48];
        load_row(w, Whh1 + g * HH);
        const int idx = g % HH;
        const bool is_g = (g >= 2 * HH) && (g < 3 * HH);

        float c[B4];
        const float* xpb[B4];
        float* hb[B4];
#pragma unroll
        for (int s = 0; s < B4; s++) {
            c[s] = __ldg(&c0in[HH + idx]);
            if (g < HH) h_sh[s * HH + g] = __ldg(&h0in[HH + g]);
            xpb[s] = g_xp1 + (size_t)(bbase + s) * SEQ * GG;
            hb[s]  = g_h1seq + (size_t)(bbase + s) * SEQ * HH;
        }
        __syncthreads();

#pragma unroll 1
        for (int t0 = 0; t0 < SEQ; t0 += KW) {
            const int par = (t0 / KW) & 1;
            if (g < B4) wait_ge(&g_progx[par * BB + bbase + g], t0 + KW);
            __syncthreads();

            float xpn[B4];
#pragma unroll
            for (int s = 0; s < B4; s++) xpn[s] = xpb[s][(size_t)t0 * GG + g];

#pragma unroll 1
            for (int tt = 0; tt < KW; tt++) {
                const int t  = t0 + tt;
                const int tn = t0 + ((tt + 1 < KW) ? (tt + 1) : tt);   // stay inside chunk
#pragma unroll
                for (int s = 0; s < B4; s++) {
                    float xp = xpn[s];
                    xpn[s] = xpb[s][(size_t)tn * GG + g];
                    float dot = dotv(w, h_sh + s * HH, xp);
                    gate_sh[s * GG + g] = is_g ? tanh_f(dot) : sigmoid_f(dot);
                }
                __syncthreads();
#pragma unroll
                for (int s = 0; s < B4; s++) {
                    float iv = gate_sh[s * GG + idx];
                    float fv = gate_sh[s * GG + idx + HH];
                    float gv = gate_sh[s * GG + idx + 2 * HH];
                    float ov = gate_sh[s * GG + idx + 3 * HH];
                    c[s] = fmaf(fv, c[s], iv * gv);
                    float hval = ov * tanh_f(c[s]);
                    if (g < HH) {
                        h_sh[s * HH + g] = hval;
                        hb[s][(size_t)t * HH + g] = hval;
                    }
                }
                __syncthreads();
            }
            if (g < B4) {
                __threadfence();
                atomicExch(&g_prog1[bbase + g], t0 + KW);
            }
        }
    } else {
        // ---------------- head workers: out[b,t] = h1[b,t,:]·head_w + head_b ----------------
        const int b = bid - 20;
        float4 wv[24];
        const float4* wp = (const float4*)head_w;
#pragma unroll
        for (int k = 0; k < 24; k++) wv[k] = __ldg(&wp[k]);
        const float hb0 = __ldg(&head_b[0]);
        const float* h1b = g_h1seq + (size_t)b * SEQ * HH;
        float* ob = out + (size_t)b * SEQ;

#pragma unroll 1
        for (int t0 = 0; t0 < SEQ; t0 += HC) {
            if (g == 0) wait_ge(&g_prog1[b], t0 + HC);
            __syncthreads();
            if (g < HC) {
                const float4* hp = (const float4*)(h1b + (size_t)(t0 + g) * HH);
                float acc = 0.0f;
#pragma unroll
                for (int k = 0; k < 24; k++) {
                    float4 a = hp[k];
                    acc += a.x * wv[k].x + a.y * wv[k].y + a.z * wv[k].z + a.w * wv[k].w;
                }
                ob[t0 + g] = acc + hb0;
            }
        }
    }
}

// =====================================================================
// launch
// =====================================================================
extern "C" void kernel_launch(void* const* d_in, const int* in_sizes, int n_in,
                              void* d_out, int out_size)
{
    (void)in_sizes; (void)n_in; (void)out_size;
    const float* x      = (const float*)d_in[0];
    const float* W_ih_0 = (const float*)d_in[1];
    const float* W_hh_0 = (const float*)d_in[2];
    const float* b_0    = (const float*)d_in[3];
    const float* W_ih_1 = (const float*)d_in[4];
    const float* W_hh_1 = (const float*)d_in[5];
    const float* b_1    = (const float*)d_in[6];
    const float* h0     = (const float*)d_in[7];
    const float* c0     = (const float*)d_in[8];
    const float* head_w = (const float*)d_in[9];
    const float* head_b = (const float*)d_in[10];
    float* out = (float*)d_out;

    reset_kernel<<<1, 32>>>();
    mega_kernel<<<28, GG>>>(x, W_ih_0, W_hh_0, b_0, W_ih_1, W_hh_1, b_1,
                            h0, c0, head_w, head_b, out);
}

// round 3
// speedup vs baseline: 2.6213x; 2.6213x over previous
#include <cuda_runtime.h>

// ---------------- problem constants ----------------
#define BB  8
#define SEQ 32768
#define HH  96
#define GG  384        // 4*HH
#define KW  16         // progress publish / consume granularity (timesteps)
#define HC  256        // head chunk

typedef unsigned long long ull;

// ---------------- scratch (device globals; allocation is banned) ----------------
__device__ float g_h0seq[(size_t)BB * SEQ * HH];   // layer-0 hidden outputs
__device__ float g_xp1 [(size_t)BB * SEQ * GG];    // layer-1 input projections (incl. b1)
__device__ float g_h1seq[(size_t)BB * SEQ * HH];   // layer-1 hidden outputs

// progress flags (timesteps completed); reset each replay by reset_kernel
__device__ int g_prog0[BB];        // layer-0 recurrence progress
__device__ int g_progx[2 * BB];    // xp1 progress, [parity][batch]
__device__ int g_prog1[BB];        // layer-1 recurrence progress

// ---------------- packed f32x2 helpers ----------------
__device__ __forceinline__ ull ffma2(ull a, ull b, ull c) {
    ull d;
    asm("fma.rn.f32x2 %0, %1, %2, %3;" : "=l"(d) : "l"(a), "l"(b), "l"(c));
    return d;
}
__device__ __forceinline__ ull pack2(float x, float y) {
    ull v;
    asm("mov.b64 %0, {%1, %2};" : "=l"(v) : "f"(x), "f"(y));
    return v;
}
__device__ __forceinline__ void unpack2(ull v, float& x, float& y) {
    asm("mov.b64 {%0, %1}, %2;" : "=f"(x), "=f"(y) : "l"(v));
}

__device__ __forceinline__ float tanh_f(float x) {
    float e = __expf(2.0f * x);
    return 1.0f - __fdividef(2.0f, 1.0f + e);
}

// ---------------- weight row -> registers ----------------
__device__ __forceinline__ void load_row(ull* w, const float* rowp) {
    const ulonglong2* wp = (const ulonglong2*)rowp;
#pragma unroll
    for (int k = 0; k < 24; k++) {
        ulonglong2 v = __ldg(wp + k);
        w[2 * k]     = v.x;
        w[2 * k + 1] = v.y;
    }
}

// dot(w_row, h[0..95]) + init ; h 16B-aligned in smem
__device__ __forceinline__ float dotv(const ull* __restrict__ w,
                                      const float* __restrict__ hsh,
                                      float init) {
    ull a0 = pack2(init, 0.0f);
    ull a1 = 0ull;
    const ulonglong2* h4 = (const ulonglong2*)hsh;
#pragma unroll
    for (int k = 0; k < 24; k++) {
        ulonglong2 hv = h4[k];
        a0 = ffma2(w[2 * k],     hv.x, a0);
        a1 = ffma2(w[2 * k + 1], hv.y, a1);
    }
    float x0, y0, x1, y1;
    unpack2(a0, x0, y0);
    unpack2(a1, x1, y1);
    return (x0 + x1) + (y0 + y1);
}

// select among the 4 gate values gathered by shfl.bfly
__device__ __forceinline__ float pick4(int m, float a0, float a1, float a2, float a3) {
    return (m == 0) ? a0 : ((m == 1) ? a1 : ((m == 2) ? a2 : a3));
}

// acquire-spin until *p >= target
__device__ __forceinline__ void wait_ge(int* p, int target) {
    while (atomicAdd(p, 0) < target) { __nanosleep(64); }
    __threadfence();
}

// ---------------- reset kernel ----------------
__global__ void reset_kernel() {
    int i = threadIdx.x;
    if (i < BB)     g_prog0[i] = 0;
    if (i < 2 * BB) g_progx[i] = 0;
    if (i < BB)     g_prog1[i] = 0;
}

// =====================================================================
// Mega-kernel: 40 blocks x 384 threads, all wave-1 co-resident.
//   0..7   : layer-0 recurrence (1 batch each)
//   8..23  : xp1 workers (2 per batch, parity interleave)
//   24..31 : layer-1 recurrence (1 batch each)
//   32..39 : head workers (1 per batch)
// =====================================================================
__global__ void __launch_bounds__(GG, 1)
mega_kernel(const float* __restrict__ x,
            const float* __restrict__ Wih0, const float* __restrict__ Whh0,
            const float* __restrict__ bv0,
            const float* __restrict__ Wih1, const float* __restrict__ Whh1,
            const float* __restrict__ bv1,
            const float* __restrict__ h0in, const float* __restrict__ c0in,
            const float* __restrict__ head_w, const float* __restrict__ head_b,
            float* __restrict__ out)
{
    __shared__ __align__(16) float sh[KW * HH];   // 6 KB; recurrences use first 2*HH
    const int bid = blockIdx.x;
    const int g   = threadIdx.x;

    if (bid < 8) {
        // ======== layer-0 recurrence, batch b ========
        const int b   = bid;
        const int wid = g >> 5, l = g & 31;
        const int j   = (wid << 3) + (l >> 2);   // hidden unit 0..95
        const int q   = l & 3;                   // gate: 0 i, 1 f, 2 g, 3 o
        const int r   = q * HH + j;              // weight/gate row

        ull w[48];
        load_row(w, Whh0 + r * HH);
        const float wih  = __ldg(&Wih0[r]);
        const float bias = __ldg(&bv0[r]);
        const float s_ = (q == 2) ? 2.0f : 1.0f;   // act = s_/(1+e^{-s_*x}) + d_
        const float d_ = (q == 2) ? -1.0f : 0.0f;

        float c = __ldg(&c0in[j]);
        if (g < HH) sh[g] = __ldg(&h0in[g]);       // buf 0
        __syncthreads();

        const float* xb = x + (size_t)b * SEQ;
        float* hb = g_h0seq + (size_t)b * SEQ * HH;
        float xnext = __ldg(&xb[0]);

#pragma unroll 1
        for (int t = 0; t < SEQ; t++) {
            const float* hr = sh + (t & 1) * HH;
            float*       hw = sh + ((t + 1) & 1) * HH;
            float xt = xnext;
            xnext = __ldg(&xb[(t + 1 < SEQ) ? (t + 1) : t]);

            float dot = dotv(w, hr, fmaf(xt, wih, bias));
            float e   = __expf(-s_ * dot);
            float act = __fdividef(s_, 1.0f + e) + d_;

            float x1 = __shfl_xor_sync(0xFFFFFFFFu, act, 1);
            float x2 = __shfl_xor_sync(0xFFFFFFFFu, act, 2);
            float x3 = __shfl_xor_sync(0xFFFFFFFFu, act, 3);
            float iv = pick4(q,     act, x1, x2, x3);
            float fv = pick4(q ^ 1, act, x1, x2, x3);
            float gv = pick4(q ^ 2, act, x1, x2, x3);
            float ov = pick4(q ^ 3, act, x1, x2, x3);

            c = fmaf(fv, c, iv * gv);
            float hval = ov * tanh_f(c);
            if (q == 0) {
                hw[j] = hval;
                hb[(size_t)t * HH + j] = hval;
            }
            __syncthreads();
            if (((t & (KW - 1)) == (KW - 1)) && g == 0) {
                __threadfence();
                atomicExch(&g_prog0[b], t + 1);
            }
        }
    } else if (bid < 24) {
        // ======== xp1 workers ========
        const int i   = bid - 8;
        const int b   = i >> 1;
        const int par = i & 1;

        ull w[48];
        load_row(w, Wih1 + g * HH);
        const float bias = __ldg(&bv1[g]);
        const float* hbase = g_h0seq + (size_t)b * SEQ * HH;
        float* xpb = g_xp1 + (size_t)b * SEQ * GG;

#pragma unroll 1
        for (int t0 = par * KW; t0 < SEQ; t0 += 2 * KW) {
            if (g == 0) wait_ge(&g_prog0[b], t0 + KW);
            __syncthreads();
            ((float4*)sh)[g] = ((const float4*)(hbase + (size_t)t0 * HH))[g];
            __syncthreads();
#pragma unroll 4
            for (int s = 0; s < KW; s++)
                xpb[(size_t)(t0 + s) * GG + g] = dotv(w, sh + s * HH, bias);
            __syncthreads();
            if (g == 0) {
                __threadfence();
                atomicExch(&g_progx[par * BB + b], t0 + KW);
            }
        }
    } else if (bid < 32) {
        // ======== layer-1 recurrence, batch b ========
        const int b   = bid - 24;
        const int wid = g >> 5, l = g & 31;
        const int j   = (wid << 3) + (l >> 2);
        const int q   = l & 3;
        const int r   = q * HH + j;

        ull w[48];
        load_row(w, Whh1 + r * HH);
        const float s_ = (q == 2) ? 2.0f : 1.0f;
        const float d_ = (q == 2) ? -1.0f : 0.0f;

        float c = __ldg(&c0in[HH + j]);
        if (g < HH) sh[g] = __ldg(&h0in[HH + g]);
        __syncthreads();

        const float* xpb = g_xp1 + (size_t)b * SEQ * GG;
        float* hb = g_h1seq + (size_t)b * SEQ * HH;

#pragma unroll 1
        for (int t0 = 0; t0 < SEQ; t0 += KW) {
            const int par = (t0 / KW) & 1;
            if (g == 0) wait_ge(&g_progx[par * BB + b], t0 + KW);
            __syncthreads();

            float xpn = xpb[(size_t)t0 * GG + r];
#pragma unroll 1
            for (int tt = 0; tt < KW; tt++) {
                const int t  = t0 + tt;
                const int tn = t0 + ((tt + 1 < KW) ? (tt + 1) : tt);
                const float* hr = sh + (t & 1) * HH;
                float*       hw = sh + ((t + 1) & 1) * HH;

                float xp = xpn;
                xpn = xpb[(size_t)tn * GG + r];

                float dot = dotv(w, hr, xp);
                float e   = __expf(-s_ * dot);
                float act = __fdividef(s_, 1.0f + e) + d_;

                float x1 = __shfl_xor_sync(0xFFFFFFFFu, act, 1);
                float x2 = __shfl_xor_sync(0xFFFFFFFFu, act, 2);
                float x3 = __shfl_xor_sync(0xFFFFFFFFu, act, 3);
                float iv = pick4(q,     act, x1, x2, x3);
                float fv = pick4(q ^ 1, act, x1, x2, x3);
                float gv = pick4(q ^ 2, act, x1, x2, x3);
                float ov = pick4(q ^ 3, act, x1, x2, x3);

                c = fmaf(fv, c, iv * gv);
                float hval = ov * tanh_f(c);
                if (q == 0) {
                    hw[j] = hval;
                    hb[(size_t)t * HH + j] = hval;
                }
                __syncthreads();
            }
            if (g == 0) {
                __threadfence();
                atomicExch(&g_prog1[b], t0 + KW);
            }
        }
    } else {
        // ======== head workers ========
        const int b = bid - 32;
        float4 wv[24];
        const float4* wp = (const float4*)head_w;
#pragma unroll
        for (int k = 0; k < 24; k++) wv[k] = __ldg(&wp[k]);
        const float hb0 = __ldg(&head_b[0]);
        const float* h1b = g_h1seq + (size_t)b * SEQ * HH;
        float* ob = out + (size_t)b * SEQ;

#pragma unroll 1
        for (int t0 = 0; t0 < SEQ; t0 += HC) {
            if (g == 0) wait_ge(&g_prog1[b], t0 + HC);
            __syncthreads();
            if (g < HC) {
                const float4* hp = (const float4*)(h1b + (size_t)(t0 + g) * HH);
                float acc = 0.0f;
#pragma unroll
                for (int k = 0; k < 24; k++) {
                    float4 a = hp[k];
                    acc += a.x * wv[k].x + a.y * wv[k].y + a.z * wv[k].z + a.w * wv[k].w;
                }
                ob[t0 + g] = acc + hb0;
            }
        }
    }
}

// =====================================================================
// launch
// =====================================================================
extern "C" void kernel_launch(void* const* d_in, const int* in_sizes, int n_in,
                              void* d_out, int out_size)
{
    (void)in_sizes; (void)n_in; (void)out_size;
    const float* x      = (const float*)d_in[0];
    const float* W_ih_0 = (const float*)d_in[1];
    const float* W_hh_0 = (const float*)d_in[2];
    const float* b_0    = (const float*)d_in[3];
    const float* W_ih_1 = (const float*)d_in[4];
    const float* W_hh_1 = (const float*)d_in[5];
    const float* b_1    = (const float*)d_in[6];
    const float* h0     = (const float*)d_in[7];
    const float* c0     = (const float*)d_in[8];
    const float* head_w = (const float*)d_in[9];
    const float* head_b = (const float*)d_in[10];
    float* out = (float*)d_out;

    reset_kernel<<<1, 32>>>();
    mega_kernel<<<40, GG>>>(x, W_ih_0, W_hh_0, b_0, W_ih_1, W_hh_1, b_1,
                            h0, c0, head_w, head_b, out);
}